// round 7
// baseline (speedup 1.0000x reference)
#include <cuda_runtime.h>

#define RB 64
#define RT 2048
#define RD 256
#define RV 256

// ---- device-global scratch (allocation-free per harness rules) ----
static __device__ float g_EWx[RV * RD];                 // E @ Wx^T   [tok][e]
static __device__ float g_EWg[RV * RD];                 // sigmoid(E @ Wz^T)
static __device__ float g_y[(size_t)RB * RT * RD];      // gated hidden states

// packed fp32x2 FMA: 2 independent bit-exact fp32 FMAs per instruction
#define FMA2(acc, h, w) \
    asm("fma.rn.f32x2 %0, %1, %2, %0;" : "+l"(acc) : "l"(h), "l"(w))

__device__ __forceinline__ float f2lo(unsigned long long v) {
    return __uint_as_float((unsigned)v);
}
__device__ __forceinline__ float f2hi(unsigned long long v) {
    return __uint_as_float((unsigned)(v >> 32));
}

// ============================================================
// Kernel 1: token tables (V=256 -> projections depend only on token id)
// ============================================================
__global__ void precompute_kernel(const float* __restrict__ E,
                                  const float* __restrict__ Wxw,
                                  const float* __restrict__ Wzw) {
    __shared__ __align__(16) float er[RD];
    const int v = blockIdx.x & (RV - 1);
    const int which = blockIdx.x >> 8;
    const float* __restrict__ W = which ? Wzw : Wxw;
    const int e = threadIdx.x;
    er[e] = E[v * RD + e];
    __syncthreads();
    const float4* w4 = (const float4*)(W + e * RD);
    const float4* e4 = (const float4*)er;
    float acc = 0.f;
#pragma unroll 16
    for (int q = 0; q < RD / 4; q++) {
        float4 a = e4[q];
        float4 b = w4[q];
        acc += a.x * b.x; acc += a.y * b.y; acc += a.z * b.z; acc += a.w * b.w;
    }
    if (which) g_EWg[v * RD + e] = 1.f / (1.f + expf(-acc));
    else       g_EWx[v * RD + e] = acc;
}

// ============================================================
// Kernel 2: sequential scan, 2-CTA cluster per batch element.
// Thread t: row r = t>>2 (global row c*128+r), k-chunk q = t&3 (64 k each,
// spanning the FULL 256-wide h). Wh slice = 32 packed f32x2 in registers.
// Per step: 1 mbarrier acquire-wait -> 32 FFMA2 matvec -> 2x shfl.bfly
// 4-lane reduce -> lane q==0: tanh, y store, h store local+remote (dbl-buf
// full-h image, padded chunk stride 68), release-arrive on both mbars
// (count 256 = 128 local + 128 remote). No bar.sync in the loop.
// ============================================================
#define SCAN_THREADS 512
#define HCH 68                         // padded h-chunk stride (floats)
#define SCAN_PAD_BYTES (120 * 1024)    // occupancy limiter: 1 CTA/SM

__device__ __forceinline__ float tanh_acc(float x) {
    x = fminf(fmaxf(x, -15.f), 15.f);
    float e = __expf(2.f * x);
    return (e - 1.f) / (e + 1.f);
}

__device__ __forceinline__ unsigned smem_u32(const void* p) {
    return (unsigned)__cvta_generic_to_shared(p);
}

__global__ __launch_bounds__(SCAN_THREADS, 1) __cluster_dims__(2, 1, 1)
void scan_kernel(const int* __restrict__ tokens, const float* __restrict__ Whw) {
    __shared__ __align__(16) float sm_h[2][4 * HCH];   // full h, dbl-buffered
    __shared__ __align__(8)  unsigned long long mbar[2];
    extern __shared__ float sm_pad[];                  // unused (occupancy)

    const int b    = blockIdx.x >> 1;
    const int c    = blockIdx.x & 1;       // cluster rank
    const int peer = c ^ 1;
    const int t = threadIdx.x;
    const int r = t >> 2;                  // local output row 0..127
    const int q = t & 3;                   // k chunk 0..3

    if (t == 0) {
        unsigned m0 = smem_u32(&mbar[0]);
        unsigned m1 = smem_u32(&mbar[1]);
        asm volatile("mbarrier.init.shared.b64 [%0], 256;" :: "r"(m0) : "memory");
        asm volatile("mbarrier.init.shared.b64 [%0], 256;" :: "r"(m1) : "memory");
    }
    for (int i = t; i < 2 * 4 * HCH; i += SCAN_THREADS)
        (&sm_h[0][0])[i] = 0.f;
    __syncthreads();
    // cluster barrier: peers' mbarriers live before any remote traffic
    asm volatile("barrier.cluster.arrive.aligned;" ::: "memory");
    asm volatile("barrier.cluster.wait.aligned;"   ::: "memory");

    // ---- Wh row j = c*128+r, k in [q*64, q*64+64): 32 packed pairs ----
    const int j = c * 128 + r;
    unsigned long long whp[32];
    {
        const ulonglong2* wr = (const ulonglong2*)(Whw + j * RD + q * 64);
#pragma unroll
        for (int i = 0; i < 16; i++) {
            ulonglong2 vv = wr[i];
            whp[2 * i]     = vv.x;
            whp[2 * i + 1] = vv.y;
        }
    }

    // writer-lane addresses (q==0): my h slot in both buffers, local+peer
    const int myk   = c * 128 + r;
    const int myoff = (myk >> 6) * HCH + (myk & 63);
    unsigned lsts[2], rrecv[2], rmbar[2];
    lsts[0] = smem_u32(&sm_h[0][myoff]);
    lsts[1] = smem_u32(&sm_h[1][myoff]);
    {
        unsigned a0 = smem_u32(&mbar[0]), a1 = smem_u32(&mbar[1]);
        asm("mapa.shared::cluster.u32 %0, %1, %2;" : "=r"(rmbar[0]) : "r"(a0), "r"(peer));
        asm("mapa.shared::cluster.u32 %0, %1, %2;" : "=r"(rmbar[1]) : "r"(a1), "r"(peer));
        asm("mapa.shared::cluster.u32 %0, %1, %2;" : "=r"(rrecv[0]) : "r"(lsts[0]), "r"(peer));
        asm("mapa.shared::cluster.u32 %0, %1, %2;" : "=r"(rrecv[1]) : "r"(lsts[1]), "r"(peer));
    }
    const unsigned lmbar0 = smem_u32(&mbar[0]);
    const unsigned lmbar1 = smem_u32(&mbar[1]);

    const int* tb = tokens + b * RT;
    float*     yb = g_y + (size_t)b * RT * RD + c * 128;

    int pp0 = 0, pp1 = 0;                  // wait parity per buffer
    int tok = tb[0];
    float wxv = 0.f, gv = 0.f;
    if (q == 0) {
        wxv = __ldg(g_EWx + tok * RD + c * 128 + r);
        gv  = __ldg(g_EWg + tok * RD + c * 128 + r);
    }

    for (int step = 0; step < RT; step++) {
        const int buf = step & 1;
        const int nb  = buf ^ 1;
        const int ntok = (step + 1 < RT) ? tb[step + 1] : 0;

        if (step > 0) {
            const unsigned lmb = buf ? lmbar1 : lmbar0;
            const unsigned par = (unsigned)(buf ? pp1 : pp0);
            unsigned done;
            do {
                asm volatile(
                    "{.reg .pred p;\n\t"
                    "mbarrier.try_wait.parity.acquire.cluster.shared::cta.b64 p, [%1], %2, 0x989680;\n\t"
                    "selp.b32 %0, 1, 0, p;}"
                    : "=r"(done) : "r"(lmb), "r"(par) : "memory");
            } while (!done);
            if (buf) pp1 ^= 1; else pp0 ^= 1;
        }

        // matvec: 32 packed FFMA2 over my 64-k chunk
        const ulonglong2* hb = (const ulonglong2*)(&sm_h[buf][q * HCH]);
        unsigned long long a0 = 0ull, a1 = 0ull, a2 = 0ull, a3 = 0ull;
#pragma unroll
        for (int i = 0; i < 16; i += 2) {
            ulonglong2 h0 = hb[i];
            ulonglong2 h1 = hb[i + 1];
            FMA2(a0, h0.x, whp[2 * i]);
            FMA2(a1, h0.y, whp[2 * i + 1]);
            FMA2(a2, h1.x, whp[2 * i + 2]);
            FMA2(a3, h1.y, whp[2 * i + 3]);
        }
        float s = ((f2lo(a0) + f2hi(a0)) + (f2lo(a1) + f2hi(a1))) +
                  ((f2lo(a2) + f2hi(a2)) + (f2lo(a3) + f2hi(a3)));
        // 4-lane butterfly reduce (lanes q=0..3 of each group)
        s += __shfl_xor_sync(0xffffffffu, s, 1);
        s += __shfl_xor_sync(0xffffffffu, s, 2);

        if (q == 0) {
            float hn = tanh_acc(wxv + s);
            yb[(size_t)step * RD + r] = hn * gv;       // 32B/warp coalesced
            // local h store + cta-scope release arrive
            asm volatile("st.shared.f32 [%0], %1;"
                         :: "r"(lsts[nb]), "f"(hn) : "memory");
            asm volatile("mbarrier.arrive.release.cta.shared::cta.b64 _, [%0];"
                         :: "r"(nb ? lmbar1 : lmbar0) : "memory");
            // remote h store + cluster-scope release arrive
            asm volatile("st.shared::cluster.f32 [%0], %1;"
                         :: "r"(rrecv[nb]), "f"(hn) : "memory");
            asm volatile("mbarrier.arrive.release.cluster.shared::cluster.b64 _, [%0];"
                         :: "r"(rmbar[nb]) : "memory");
            // prefetch next token rows (latency hidden under next step)
            wxv = __ldg(g_EWx + ntok * RD + c * 128 + r);
            gv  = __ldg(g_EWg + ntok * RD + c * 128 + r);
        }
        tok = ntok;
    }

    // drain: no CTA exits while the peer may still arrive on its mbars
    asm volatile("barrier.cluster.arrive.aligned;" ::: "memory");
    asm volatile("barrier.cluster.wait.aligned;"   ::: "memory");
    (void)sm_pad;
}

// ============================================================
// Kernel 3: tied head.  out[m][v] = sum_d Y[m][d] * E[v][d]
// 128x128x16 smem-tiled GEMM, 8x8 microtiles, FFMA2 inner product.
// ============================================================
#define HT 256
__global__ __launch_bounds__(HT, 2)
void head_kernel(const float* __restrict__ E, float* __restrict__ out) {
    __shared__ __align__(16) float As[16][128 + 4];
    __shared__ __align__(16) float Bs[16][128 + 4];
    const float* __restrict__ Y = g_y;
    const int m0 = blockIdx.y * 128;
    const int n0 = blockIdx.x * 128;
    const int tid = threadIdx.x;
    const int tx = tid & 15, ty = tid >> 4;

    unsigned long long cd[8][4];           // 8 rows x 4 packed col-pairs
#pragma unroll
    for (int i = 0; i < 8; i++)
#pragma unroll
        for (int jj = 0; jj < 4; jj++) cd[i][jj] = 0ull;

    for (int kk = 0; kk < RD; kk += 16) {
#pragma unroll
        for (int l = 0; l < 2; l++) {
            int idx = tid + l * HT;
            int m   = idx >> 2;
            int kq  = idx & 3;
            float4 av = *(const float4*)(Y + (size_t)(m0 + m) * RD + kk + kq * 4);
            As[kq * 4 + 0][m] = av.x; As[kq * 4 + 1][m] = av.y;
            As[kq * 4 + 2][m] = av.z; As[kq * 4 + 3][m] = av.w;
            float4 bv = *(const float4*)(E + (size_t)(n0 + m) * RD + kk + kq * 4);
            Bs[kq * 4 + 0][m] = bv.x; Bs[kq * 4 + 1][m] = bv.y;
            Bs[kq * 4 + 2][m] = bv.z; Bs[kq * 4 + 3][m] = bv.w;
        }
        __syncthreads();
#pragma unroll
        for (int k = 0; k < 16; k++) {
            float a[8];
            *(float4*)(a)     = *(const float4*)(&As[k][ty * 8]);
            *(float4*)(a + 4) = *(const float4*)(&As[k][ty * 8 + 4]);
            ulonglong2 b01 = *(const ulonglong2*)(&Bs[k][tx * 8]);
            ulonglong2 b23 = *(const ulonglong2*)(&Bs[k][tx * 8 + 4]);
            unsigned long long bp0 = b01.x, bp1 = b01.y;
            unsigned long long bp2 = b23.x, bp3 = b23.y;
#pragma unroll
            for (int i = 0; i < 8; i++) {
                unsigned long long ad;
                unsigned au = __float_as_uint(a[i]);
                asm("mov.b64 %0, {%1, %1};" : "=l"(ad) : "r"(au));
                FMA2(cd[i][0], ad, bp0);
                FMA2(cd[i][1], ad, bp1);
                FMA2(cd[i][2], ad, bp2);
                FMA2(cd[i][3], ad, bp3);
            }
        }
        __syncthreads();
    }
#pragma unroll
    for (int i = 0; i < 8; i++) {
        float* orow = out + (size_t)(m0 + ty * 8 + i) * RV + n0 + tx * 8;
        *(float4*)(orow)     = make_float4(f2lo(cd[i][0]), f2hi(cd[i][0]),
                                           f2lo(cd[i][1]), f2hi(cd[i][1]));
        *(float4*)(orow + 4) = make_float4(f2lo(cd[i][2]), f2hi(cd[i][2]),
                                           f2lo(cd[i][3]), f2hi(cd[i][3]));
    }
}

// ============================================================
extern "C" void kernel_launch(void* const* d_in, const int* in_sizes, int n_in,
                              void* d_out, int out_size) {
    const int*   tokens = (const int*)  d_in[0];
    const float* E      = (const float*)d_in[1];
    const float* Wxw    = (const float*)d_in[2];
    const float* Whw    = (const float*)d_in[3];
    const float* Wzw    = (const float*)d_in[4];
    float* out = (float*)d_out;

    cudaFuncSetAttribute(scan_kernel,
                         cudaFuncAttributeMaxDynamicSharedMemorySize,
                         SCAN_PAD_BYTES);

    precompute_kernel<<<2 * RV, RD>>>(E, Wxw, Wzw);
    scan_kernel<<<2 * RB, SCAN_THREADS, SCAN_PAD_BYTES>>>(tokens, Whw);
    head_kernel<<<dim3(RV / 128, (RB * RT) / 128), HT>>>(E, out);
}